// round 16
// baseline (speedup 1.0000x reference)
#include <cuda_runtime.h>
#include <cuda_fp16.h>
#include <math.h>
#include <stdint.h>

#define NN 30000
#define RR 1000
#define TT 300000
#define DD 128
#define BB 1024
#define NZ 600000
#define OUTD 768
#define GAMMA_C 3.0f

// ---------------- scratch (device globals) ----------------
__device__ float g_relhat[RR * DD];
__device__ float g_elogit[4 * RR];
__device__ float g_s[4 * NN];
__device__ float g_featE[(size_t)NN * DD];
__device__ float g_featR[(size_t)NN * DD];
__device__ __half g_fcurhA[(size_t)NN * 256];
__device__ __half g_fcurhB[(size_t)NN * 256];
__device__ __half g_embh[(size_t)NN * OUTD];
__device__ float g_nb[NN];
__device__ float g_nbmax;
// adjacency CSR (GAT graph)
__device__ int g_rowptr[NN + 1];
__device__ int g_cursor[NN];
__device__ int g_ecol[TT];
__device__ int g_erel[TT];
// averaging CSRs
__device__ int g_rowptrE[NN + 1];
__device__ int g_curE[NN];
__device__ int g_ecolE[NZ];
__device__ int g_rowptrR[NN + 1];
__device__ int g_curR[NN];
__device__ int g_ecolR[NZ];
// loss
__device__ int   g_idxA[2 * BB];
__device__ float g_na[2 * BB];
__device__ float g_pos[BB];
__device__ int   g_lp[BB];
__device__ int   g_rp[BB];
__device__ float g_scale[2 * BB];
__device__ float g_iscale[2 * BB];
__device__ __align__(16) short g_Ss[(size_t)2 * BB * NN];  // int16 row-scaled S
__device__ double g_rsum[2 * BB];
__device__ double g_rsq[2 * BB];
__device__ float  g_rmax[2 * BB];
__device__ float g_lse[2 * BB];

__device__ __forceinline__ float warp_sum(float v) {
#pragma unroll
    for (int o = 16; o > 0; o >>= 1) v += __shfl_xor_sync(0xffffffffu, v, o);
    return v;
}
__device__ __forceinline__ float warp_max(float v) {
#pragma unroll
    for (int o = 16; o > 0; o >>= 1) v = fmaxf(v, __shfl_xor_sync(0xffffffffu, v, o));
    return v;
}
__device__ __forceinline__ void atomicMaxF(float* addr, float v) {
    if (v >= 0.f) atomicMax((int*)addr, __float_as_int(v));
    else          atomicMin((unsigned int*)addr, __float_as_uint(v));
}
__device__ __forceinline__ float fast_exp(float x) {
    float t = fmaxf(x * 1.4426950408889634f, -80.0f);
    float fl = floorf(t);
    float f = t - fl;
    float p = 0.0013333558f;
    p = fmaf(p, f, 0.0096181291f);
    p = fmaf(p, f, 0.0555041086f);
    p = fmaf(p, f, 0.2402264476f);
    p = fmaf(p, f, 0.6931471806f);
    p = fmaf(p, f, 1.0f);
    int i = (int)fl;
    return p * __int_as_float((i + 127) << 23);
}
__device__ __forceinline__ uint32_t smem_u32(const void* p) {
    uint32_t a;
    asm("{ .reg .u64 t; cvta.to.shared.u64 t, %1; cvt.u32.u64 %0, t; }" : "=r"(a) : "l"(p));
    return a;
}
__device__ __forceinline__ void cpasync16(uint32_t dst, const void* src) {
    asm volatile("cp.async.cg.shared.global [%0], [%1], 16;" :: "r"(dst), "l"(src));
}
__device__ __forceinline__ void ldsm4(uint32_t* r, uint32_t addr) {
    asm volatile("ldmatrix.sync.aligned.m8n8.x4.shared.b16 {%0,%1,%2,%3}, [%4];"
                 : "=r"(r[0]), "=r"(r[1]), "=r"(r[2]), "=r"(r[3]) : "r"(addr));
}
__device__ __forceinline__ void mma_f16(float* c, const uint32_t* a, const uint32_t* b) {
    asm volatile("mma.sync.aligned.m16n8k16.row.col.f32.f16.f16.f32 "
                 "{%0,%1,%2,%3}, {%4,%5,%6,%7}, {%8,%9}, {%0,%1,%2,%3};"
                 : "+f"(c[0]), "+f"(c[1]), "+f"(c[2]), "+f"(c[3])
                 : "r"(a[0]), "r"(a[1]), "r"(a[2]), "r"(a[3]), "r"(b[0]), "r"(b[1]));
}
__device__ __forceinline__ void st_half4(__half* dst, float a, float b, float c, float d) {
    __half2 h0 = __floats2half2_rn(a, b);
    __half2 h1 = __floats2half2_rn(c, d);
    *(uint2*)dst = make_uint2(*(uint32_t*)&h0, *(uint32_t*)&h1);
}
__device__ __forceinline__ float4 ld_half4(const __half* src) {
    uint2 u = *(const uint2*)src;
    float2 f0 = __half22float2(*(__half2*)&u.x);
    float2 f1 = __half22float2(*(__half2*)&u.y);
    return make_float4(f0.x, f0.y, f1.x, f1.y);
}
__device__ __forceinline__ int* cursor_of(int w) {
    return (w == 0) ? g_cursor : (w == 1) ? g_curE : g_curR;
}
__device__ __forceinline__ int* rowptr_of(int w) {
    return (w == 0) ? g_rowptr : (w == 1) ? g_rowptrE : g_rowptrR;
}

// ---------------- init ----------------
__global__ void k_init_stats() {
    int i = blockIdx.x * blockDim.x + threadIdx.x;
    if (i < NN) { g_nb[i] = 0.f; g_cursor[i] = 0; g_curE[i] = 0; g_curR[i] = 0; }
    if (i < 2 * BB) { g_rsum[i] = 0.0; g_rsq[i] = 0.0; g_rmax[i] = -3.0e38f; }
    if (i == 0) g_nbmax = 0.f;
}

// ---------------- relation prep ----------------
__global__ void k_relprep(const float* __restrict__ rel_emb,
                          const float* __restrict__ attn_e,
                          const float* __restrict__ attn_r) {
    int gid = blockIdx.x * blockDim.x + threadIdx.x;
    int r = gid >> 5;
    if (r >= RR) return;
    int lane = gid & 31;
    int d = lane * 4;
    float4 u = *(const float4*)&rel_emb[(size_t)r * DD + d];
    float ss = u.x * u.x + u.y * u.y + u.z * u.z + u.w * u.w;
    ss = warp_sum(ss);
    float inv = 1.f / fmaxf(sqrtf(ss), 1e-12f);
    u.x *= inv; u.y *= inv; u.z *= inv; u.w *= inv;
    *(float4*)&g_relhat[r * DD + d] = u;
    const float* ks[4] = { attn_e, attn_e + DD, attn_r, attn_r + DD };
#pragma unroll
    for (int c = 0; c < 4; c++) {
        const float4 kk = *(const float4*)&ks[c][d];
        float dot = u.x * kk.x + u.y * kk.y + u.z * kk.z + u.w * kk.w;
        dot = warp_sum(dot);
        if (lane == 0) g_elogit[c * RR + r] = fast_exp(dot);
    }
}

// ---------------- CSR build ----------------
__global__ void k_csr_cnt(const int* __restrict__ rows, int n, int w) {
    int t = blockIdx.x * blockDim.x + threadIdx.x;
    if (t >= n) return;
    atomicAdd(&cursor_of(w)[rows[t]], 1);
}
__global__ void k_scan(int w) {
    int* cur = cursor_of(w);
    int* rp = rowptr_of(w);
    __shared__ int warpsum[32];
    __shared__ int s_off;
    int tid = threadIdx.x, lane = tid & 31, wd = tid >> 5;
    if (tid == 0) s_off = 0;
    __syncthreads();
    for (int base = 0; base < NN; base += 1024) {
        int i = base + tid;
        int v = (i < NN) ? cur[i] : 0;
        int x = v;
#pragma unroll
        for (int o = 1; o < 32; o <<= 1) {
            int t2 = __shfl_up_sync(0xffffffffu, x, o);
            if (lane >= o) x += t2;
        }
        if (lane == 31) warpsum[wd] = x;
        __syncthreads();
        if (wd == 0) {
            int y = warpsum[lane];
#pragma unroll
            for (int o = 1; o < 32; o <<= 1) {
                int t2 = __shfl_up_sync(0xffffffffu, y, o);
                if (lane >= o) y += t2;
            }
            warpsum[lane] = y;
        }
        __syncthreads();
        int excl = x - v + (wd > 0 ? warpsum[wd - 1] : 0) + s_off;
        if (i < NN) { rp[i] = excl; cur[i] = excl; }
        __syncthreads();
        if (tid == 1023) s_off = excl + v;
        __syncthreads();
    }
    if (tid == 0) rp[NN] = s_off;
}
__global__ void k_fill_adj(const int* __restrict__ adj, const int* __restrict__ r_index) {
    int t = blockIdx.x * blockDim.x + threadIdx.x;
    if (t >= TT) return;
    int pos = atomicAdd(&g_cursor[adj[t]], 1);
    g_ecol[pos] = adj[TT + t];
    g_erel[pos] = r_index[TT + t];
}
__global__ void k_fill_avg(const int* __restrict__ eadj, int w) {
    int t = blockIdx.x * blockDim.x + threadIdx.x;
    if (t >= NZ) return;
    int* cur = (w == 1) ? g_curE : g_curR;
    int* ec = (w == 1) ? g_ecolE : g_ecolR;
    int pos = atomicAdd(&cur[eadj[t]], 1);
    ec[pos] = eadj[NZ + t];
}

// ---------------- per-row softmax denominators ----------------
__global__ void k_rowsm() {
    int gid = blockIdx.x * blockDim.x + threadIdx.x;
    int r = gid >> 5;
    if (r >= NN) return;
    int lane = gid & 31;
    int beg = g_rowptr[r], end = g_rowptr[r + 1];
    float s[4] = { 0.f, 0.f, 0.f, 0.f };
    for (int e = beg + lane; e < end; e += 32) {
        int rel = g_erel[e];
#pragma unroll
        for (int c = 0; c < 4; c++) s[c] += g_elogit[c * RR + rel];
    }
#pragma unroll
    for (int c = 0; c < 4; c++) {
        s[c] = warp_sum(s[c]);
        if (lane == 0) g_s[c * NN + r] = (s[c] > 0.f) ? 1.f / s[c] : 0.f;
    }
}

// ---------------- neighbor-average gather ----------------
__global__ void k_avg_gather(const float* __restrict__ src, int w) {
    int gid = blockIdx.x * blockDim.x + threadIdx.x;
    int r = gid >> 5;
    if (r >= NN) return;
    int lane = gid & 31;
    int d = lane * 4;
    const int* rp = (w == 1) ? g_rowptrE : g_rowptrR;
    const int* ec = (w == 1) ? g_ecolE : g_ecolR;
    float* feat = (w == 1) ? g_featE : g_featR;
    int beg = rp[r], end = rp[r + 1];
    float4 acc = make_float4(0, 0, 0, 0);
    for (int e = beg; e < end; e++) {
        int c = __ldg(&ec[e]);
        float4 v = *(const float4*)&src[(size_t)c * DD + d];
        acc.x += v.x; acc.y += v.y; acc.z += v.z; acc.w += v.w;
    }
    float inv = (end > beg) ? 1.f / (float)(end - beg) : 0.f;
    acc.x *= inv; acc.y *= inv; acc.z *= inv; acc.w *= inv;
    *(float4*)&feat[(size_t)r * DD + d] = acc;
}

// ---------------- initial tanh ----------------
__global__ void k_tanh0() {
    int gid = blockIdx.x * blockDim.x + threadIdx.x;
    int n = gid >> 5;
    if (n >= NN) return;
    int lane = gid & 31;
    int d = lane * 4;
    float4 fe = *(const float4*)&g_featE[(size_t)n * DD + d];
    float4 fr = *(const float4*)&g_featR[(size_t)n * DD + d];
    float vE0 = tanhf(fe.x), vE1 = tanhf(fe.y), vE2 = tanhf(fe.z), vE3 = tanhf(fe.w);
    float vR0 = tanhf(fr.x), vR1 = tanhf(fr.y), vR2 = tanhf(fr.z), vR3 = tanhf(fr.w);
    st_half4(&g_fcurhA[(size_t)n * 256 + d], vE0, vE1, vE2, vE3);
    st_half4(&g_fcurhA[(size_t)n * 256 + 128 + d], vR0, vR1, vR2, vR3);
    __half* hrow = &g_embh[(size_t)n * OUTD];
    st_half4(hrow + d, vE0, vE1, vE2, vE3);
    st_half4(hrow + 384 + d, vR0, vR1, vR2, vR3);
    float ss = 0.f;
    float q[8] = { vE0, vE1, vE2, vE3, vR0, vR1, vR2, vR3 };
#pragma unroll
    for (int k = 0; k < 8; k++) {
        float qq = __half2float(__float2half_rn(q[k]));
        ss += qq * qq;
    }
    ss = warp_sum(ss);
    if (lane == 0) atomicAdd(&g_nb[n], ss);
}

// ---------------- GAT layer ----------------
__global__ void k_gat_layer(int l, int dir) {
    int gid = blockIdx.x * blockDim.x + threadIdx.x;
    int r = gid >> 5;
    if (r >= NN) return;
    int lane = gid & 31;
    int d = lane * 4;
    const __half* src = dir ? g_fcurhB : g_fcurhA;
    __half* dst = dir ? g_fcurhA : g_fcurhB;
    int beg = g_rowptr[r], end = g_rowptr[r + 1];
    const int cE = l, cR = 2 + l;
    const float siE = g_s[cE * NN + r];
    const float siR = g_s[cR * NN + r];
    const float* elE = &g_elogit[cE * RR];
    const float* elR = &g_elogit[cR * RR];
    float4 accE = make_float4(0, 0, 0, 0), accR = make_float4(0, 0, 0, 0);
    for (int e = beg; e < end; e++) {
        int col = __ldg(&g_ecol[e]);
        int rel = __ldg(&g_erel[e]);
        float4 u = *(const float4*)&g_relhat[rel * DD + d];
        float4 xE = ld_half4(&src[(size_t)col * 256 + d]);
        float4 xR = ld_half4(&src[(size_t)col * 256 + 128 + d]);
        float dotE = warp_sum(xE.x * u.x + xE.y * u.y + xE.z * u.z + xE.w * u.w);
        float dotR = warp_sum(xR.x * u.x + xR.y * u.y + xR.z * u.z + xR.w * u.w);
        float wE = elE[rel] * siE;
        float wR = elR[rel] * siR;
        float sE = 2.f * dotE, sR = 2.f * dotR;
        accE.x += wE * (xE.x - sE * u.x); accE.y += wE * (xE.y - sE * u.y);
        accE.z += wE * (xE.z - sE * u.z); accE.w += wE * (xE.w - sE * u.w);
        accR.x += wR * (xR.x - sR * u.x); accR.y += wR * (xR.y - sR * u.y);
        accR.z += wR * (xR.z - sR * u.z); accR.w += wR * (xR.w - sR * u.w);
    }
    float vE0 = tanhf(accE.x), vE1 = tanhf(accE.y), vE2 = tanhf(accE.z), vE3 = tanhf(accE.w);
    float vR0 = tanhf(accR.x), vR1 = tanhf(accR.y), vR2 = tanhf(accR.z), vR3 = tanhf(accR.w);
    st_half4(&dst[(size_t)r * 256 + d], vE0, vE1, vE2, vE3);
    st_half4(&dst[(size_t)r * 256 + 128 + d], vR0, vR1, vR2, vR3);
    int base = (l + 1) * DD;
    __half* hrow = &g_embh[(size_t)r * OUTD];
    st_half4(hrow + base + d, vE0, vE1, vE2, vE3);
    st_half4(hrow + 384 + base + d, vR0, vR1, vR2, vR3);
    float ss = 0.f;
    float q[8] = { vE0, vE1, vE2, vE3, vR0, vR1, vR2, vR3 };
#pragma unroll
    for (int k = 0; k < 8; k++) {
        float qq = __half2float(__float2half_rn(q[k]));
        ss += qq * qq;
    }
    ss = warp_sum(ss);
    if (lane == 0) atomicAdd(&g_nb[r], ss);
}

// ---------------- loss prep ----------------
__global__ void k_prep_pairs(const int* __restrict__ pairs) {
    int p = blockIdx.x * blockDim.x + threadIdx.x;
    if (p >= BB) return;
    int lp = pairs[2 * p], rp = pairs[2 * p + 1];
    g_lp[p] = lp; g_rp[p] = rp;
    g_idxA[p] = lp; g_idxA[BB + p] = rp;
}
__global__ void k_pairstats() {
    int gid = blockIdx.x * blockDim.x + threadIdx.x;
    int p = gid >> 5;
    if (p >= BB) return;
    int lane = gid & 31;
    int lp = g_lp[p], rp = g_rp[p];
    const __half* a = &g_embh[(size_t)lp * OUTD];
    const __half* b = &g_embh[(size_t)rp * OUTD];
    float ss = 0.f;
    for (int k = lane * 4; k < OUTD; k += 128) {
        float4 av = ld_half4(&a[k]);
        float4 bv = ld_half4(&b[k]);
        float d0 = av.x - bv.x, d1 = av.y - bv.y, d2 = av.z - bv.z, d3 = av.w - bv.w;
        ss += d0 * d0 + d1 * d1 + d2 * d2 + d3 * d3;
    }
    ss = warp_sum(ss);
    if (lane == 0) { g_pos[p] = ss; g_na[p] = g_nb[lp]; }
    if (lane == 1) g_na[BB + p] = g_nb[rp];
}
// global max of nb
__global__ void k_nbmax() {
    int i = blockIdx.x * blockDim.x + threadIdx.x;
    float v = (i < NN) ? g_nb[i] : 0.f;
    v = warp_max(v);
    __shared__ float sh[8];
    int lane = threadIdx.x & 31, wd = threadIdx.x >> 5;
    if (lane == 0) sh[wd] = v;
    __syncthreads();
    if (wd == 0) {
        v = (lane < 8) ? sh[lane] : 0.f;
        v = warp_max(v);
        if (lane == 0) atomicMaxF(&g_nbmax, v);
    }
}
// per-row quantization scale from analytic bound |S| <= |base| + nbmax + 2*sqrt(na*nbmax)
__global__ void k_scalecalc() {
    int i = blockIdx.x * blockDim.x + threadIdx.x;
    if (i >= 2 * BB) return;
    int p = i & (BB - 1);
    float base = g_pos[p] - g_na[i] + GAMMA_C;
    float nbm = g_nbmax;
    float bound = fabsf(base) + nbm + 2.f * sqrtf(fmaxf(g_na[i], 0.f) * nbm) + 1.f;
    g_scale[i] = 32000.f / bound;
    g_iscale[i] = bound * (1.f / 32000.f);
}

// ---------------- mma.sync fp16 GEMM (256x128, 512 thr) + int16 S + stats ----------------
#define JT 128
#define NS (OUTD / 16)
#define ROWB 48
#define STG_A 0
#define STG_B 12288          // A: 256 rows x 48B
#define STGB 18432           // + B: 128 rows x 48B
#define NSTG 4

__global__ __launch_bounds__(512, 1) void k_gemm_mma() {
    extern __shared__ char dynsmem[];
    __shared__ int s_idx[256];
    const int tid = threadIdx.x;
    const int wid = tid >> 5;
    const int lane = tid & 31;
    const int warp_m = wid & 3;      // 4 warps in m (64 rows each) -> 256
    const int warp_n = wid >> 2;     // 4 warps in n (32 cols each) -> 128
    const int bm = blockIdx.x;
    const int jbase = blockIdx.y * JT;
    const uint32_t sbase = smem_u32(dynsmem);

    if (tid < 256) s_idx[tid] = g_idxA[bm * 256 + tid];
    __syncthreads();

    // A loader: all 512 threads (256 rows x 2 16B-chunks)
    const int arow = tid >> 1;
    const int ahalf = tid & 1;
    const __half* gaPtr = g_embh + (size_t)s_idx[arow] * OUTD + ahalf * 8;
    const uint32_t dOffA = arow * ROWB + ahalf * 16;
    // B loader: threads < 256 (128 rows x 2 chunks)
    const int brow = (tid & 255) >> 1;
    const int bhalf = tid & 1;
    int jld = jbase + brow;
    if (jld >= NN) jld = 0;
    const __half* gbPtr = g_embh + (size_t)jld * OUTD + bhalf * 8;
    const uint32_t dOffB = STG_B + brow * ROWB + bhalf * 16;
    const bool bldr = (tid < 256);

#pragma unroll
    for (int p = 0; p < 3; p++) {
        uint32_t sb = sbase + p * STGB;
        cpasync16(sb + STG_A + dOffA, gaPtr + p * 16);
        if (bldr) cpasync16(sb + dOffB, gbPtr + p * 16);
        asm volatile("cp.async.commit_group;" ::: "memory");
    }

    float acc[4][4][4] = {};
    const int rsel = lane & 15;
    const int csel = (lane >> 4) * 16;

    for (int it = 0; it < NS; it++) {
        if (it < NS - 2)       asm volatile("cp.async.wait_group 2;" ::: "memory");
        else if (it == NS - 2) asm volatile("cp.async.wait_group 1;" ::: "memory");
        else                   asm volatile("cp.async.wait_group 0;" ::: "memory");
        __syncthreads();

        if (it + 3 < NS) {
            uint32_t sb = sbase + ((it + 3) & 3) * STGB;
            cpasync16(sb + STG_A + dOffA, gaPtr + (it + 3) * 16);
            if (bldr) cpasync16(sb + dOffB, gbPtr + (it + 3) * 16);
            asm volatile("cp.async.commit_group;" ::: "memory");
        }

        const uint32_t sb = sbase + (it & 3) * STGB;
        uint32_t aF[4][4], bF[4][2];
#pragma unroll
        for (int mt = 0; mt < 4; mt++) {
            uint32_t ad = sb + STG_A + (uint32_t)((warp_m * 64 + mt * 16 + rsel) * ROWB + csel);
            ldsm4(aF[mt], ad);
        }
#pragma unroll
        for (int tp = 0; tp < 2; tp++) {
            uint32_t bd = sb + STG_B + (uint32_t)((warp_n * 32 + tp * 16 + rsel) * ROWB + csel);
            uint32_t r[4];
            ldsm4(r, bd);
            bF[tp * 2][0] = r[0]; bF[tp * 2][1] = r[2];
            bF[tp * 2 + 1][0] = r[1]; bF[tp * 2 + 1][1] = r[3];
        }
#pragma unroll
        for (int mt = 0; mt < 4; mt++)
#pragma unroll
            for (int nt = 0; nt < 4; nt++)
                mma_f16(acc[mt][nt], aF[mt], bF[nt]);
    }

    const int lq = lane >> 2;
    const int lr = lane & 3;
    float2 nbv[4];
#pragma unroll
    for (int nt = 0; nt < 4; nt++) {
        int j0 = jbase + warp_n * 32 + nt * 8 + 2 * lr;
        nbv[nt].x = (j0 < NN) ? g_nb[j0] : 0.f;
        nbv[nt].y = (j0 + 1 < NN) ? g_nb[j0 + 1] : 0.f;
    }
#pragma unroll
    for (int mt = 0; mt < 4; mt++) {
#pragma unroll
        for (int h = 0; h < 2; h++) {
            const int i = bm * 256 + warp_m * 64 + mt * 16 + lq + h * 8;
            const int p = i & (BB - 1);
            const float base = g_pos[p] - g_na[i] + GAMMA_C;
            const int lp = g_lp[p], rp = g_rp[p];
            const float sc = g_scale[i], isc = g_iscale[i];
            float s = 0.f, q = 0.f, mx = -3.0e38f;
            short* srow = &g_Ss[(size_t)i * NN];
#pragma unroll
            for (int nt = 0; nt < 4; nt++) {
                int j0 = jbase + warp_n * 32 + nt * 8 + 2 * lr;
                float c0 = acc[mt][nt][h * 2 + 0];
                float c1 = acc[mt][nt][h * 2 + 1];
                if (j0 + 1 < NN) {
                    float v0 = (base - nbv[nt].x + 2.f * c0) *
                               (1.f - (float)(j0 == lp) - (float)(j0 == rp));
                    float v1 = (base - nbv[nt].y + 2.f * c1) *
                               (1.f - (float)(j0 + 1 == lp) - (float)(j0 + 1 == rp));
                    int q0 = __float2int_rn(v0 * sc);
                    int q1 = __float2int_rn(v1 * sc);
                    q0 = max(-32767, min(32767, q0));
                    q1 = max(-32767, min(32767, q1));
                    *(short2*)&srow[j0] = make_short2((short)q0, (short)q1);
                    float d0 = (float)q0 * isc, d1 = (float)q1 * isc;
                    s += d0 + d1; q += d0 * d0 + d1 * d1;
                    mx = fmaxf(mx, fmaxf(d0, d1));
                } else if (j0 < NN) {
                    float v0 = (base - nbv[nt].x + 2.f * c0) *
                               (1.f - (float)(j0 == lp) - (float)(j0 == rp));
                    int q0 = __float2int_rn(v0 * sc);
                    q0 = max(-32767, min(32767, q0));
                    srow[j0] = (short)q0;
                    float d0 = (float)q0 * isc;
                    s += d0; q += d0 * d0; mx = fmaxf(mx, d0);
                }
            }
#pragma unroll
            for (int o = 1; o <= 2; o <<= 1) {
                s += __shfl_xor_sync(0xffffffffu, s, o);
                q += __shfl_xor_sync(0xffffffffu, q, o);
                mx = fmaxf(mx, __shfl_xor_sync(0xffffffffu, mx, o));
            }
            if (lr == 0) {
                atomicAdd(&g_rsum[i], (double)s);
                atomicAdd(&g_rsq[i], (double)q);
                atomicMaxF(&g_rmax[i], mx);
            }
        }
    }
}

// ---------------- per-row logsumexp (int16 S) ----------------
__global__ void k_row_exp() {
    int i = blockIdx.x;
    int tid = threadIdx.x;
    double mu_d = g_rsum[i] / NN;
    double var = g_rsq[i] / NN - mu_d * mu_d;
    if (var < 0.0) var = 0.0;
    double sd = sqrt(var);
    float mu = (float)mu_d;
    float inv = (float)(20.0 / sd);
    float zmax = (float)((g_rmax[i] - mu_d) * (20.0 / sd)) + 8.f;
    float qinv = g_iscale[i] * inv;             // z = q*qinv + cterm
    float cterm = 8.f - zmax - mu * inv;
    const int4* row4 = (const int4*)(g_Ss + (size_t)i * NN);   // 8 shorts per int4
    float es = 0.f;
    for (int j = tid; j < NN / 8; j += 256) {
        int4 v = row4[j];
        short2 s0 = *(short2*)&v.x, s1 = *(((short2*)&v.x) + 1);
        short2 s2 = *(short2*)&v.z, s3 = *(((short2*)&v.z) + 1);
        es += fast_exp(fmaf((float)s0.x, qinv, cterm));
        es += fast_exp(fmaf((float)s0.y, qinv, cterm));
        es += fast_exp(fmaf((float)s1.x, qinv, cterm));
        es += fast_exp(fmaf((float)s1.y, qinv, cterm));
        es += fast_exp(fmaf((float)s2.x, qinv, cterm));
        es += fast_exp(fmaf((float)s2.y, qinv, cterm));
        es += fast_exp(fmaf((float)s3.x, qinv, cterm));
        es += fast_exp(fmaf((float)s3.y, qinv, cterm));
    }
    __shared__ float sh[256];
    sh[tid] = es;
    __syncthreads();
    for (int o = 128; o > 0; o >>= 1) {
        if (tid < o) sh[tid] += sh[tid + o];
        __syncthreads();
    }
    if (tid == 0) g_lse[i] = zmax + logf(sh[0]);
}

__global__ void k_final(float* out) {
    int tid = threadIdx.x;
    double acc = 0.0;
    for (int p = tid; p < BB; p += 256) acc += (double)g_lse[p] + (double)g_lse[BB + p];
    __shared__ double sh[256];
    sh[tid] = acc;
    __syncthreads();
    for (int o = 128; o > 0; o >>= 1) {
        if (tid < o) sh[tid] += sh[tid + o];
        __syncthreads();
    }
    if (tid == 0) out[0] = (float)(sh[0] / BB);
}

// ---------------- driver ----------------
extern "C" void kernel_launch(void* const* d_in, const int* in_sizes, int n_in,
                              void* d_out, int out_size) {
    const float* ent_emb = (const float*)d_in[0];
    const float* rel_emb = (const float*)d_in[1];
    const float* attn_e  = (const float*)d_in[2];
    const float* attn_r  = (const float*)d_in[3];
    const int* adj     = (const int*)d_in[5];
    const int* r_index = (const int*)d_in[6];
    const int* ent_adj = (const int*)d_in[7];
    const int* rel_adj = (const int*)d_in[8];
    const int* pairs   = (const int*)d_in[9];
    float* out = (float*)d_out;

    static cudaStream_t sA = 0, sB = 0, sC = 0;
    static cudaEvent_t evRoot = 0, evA = 0, evB = 0, evC = 0;
    static bool sinit = false;
    if (!sinit) {
        cudaStreamCreateWithFlags(&sA, cudaStreamNonBlocking);
        cudaStreamCreateWithFlags(&sB, cudaStreamNonBlocking);
        cudaStreamCreateWithFlags(&sC, cudaStreamNonBlocking);
        cudaEventCreateWithFlags(&evRoot, cudaEventDisableTiming);
        cudaEventCreateWithFlags(&evA, cudaEventDisableTiming);
        cudaEventCreateWithFlags(&evB, cudaEventDisableTiming);
        cudaEventCreateWithFlags(&evC, cudaEventDisableTiming);
        sinit = true;
    }

    const int TPB = 256;
    const int gT   = (TT + TPB - 1) / TPB;
    const int gNZ1 = (NZ + TPB - 1) / TPB;
    const int gWN  = (NN * 32 + TPB - 1) / TPB;

    k_init_stats<<<(NN + TPB - 1) / TPB, TPB>>>();
    k_prep_pairs<<<(BB + TPB - 1) / TPB, TPB>>>(pairs);
    cudaEventRecord(evRoot, 0);
    cudaStreamWaitEvent(sA, evRoot, 0);
    cudaStreamWaitEvent(sB, evRoot, 0);
    cudaStreamWaitEvent(sC, evRoot, 0);

    // chain A: relation prep + adj CSR + softmax denominators
    k_relprep<<<(RR * 32 + TPB - 1) / TPB, TPB, 0, sA>>>(rel_emb, attn_e, attn_r);
    k_csr_cnt<<<gT, TPB, 0, sA>>>(adj, TT, 0);
    k_scan<<<1, 1024, 0, sA>>>(0);
    k_fill_adj<<<gT, TPB, 0, sA>>>(adj, r_index);
    k_rowsm<<<gWN, TPB, 0, sA>>>();
    cudaEventRecord(evA, sA);

    // chain B: entity-avg CSR + gather
    k_csr_cnt<<<gNZ1, TPB, 0, sB>>>(ent_adj, NZ, 1);
    k_scan<<<1, 1024, 0, sB>>>(1);
    k_fill_avg<<<gNZ1, TPB, 0, sB>>>(ent_adj, 1);
    k_avg_gather<<<gWN, TPB, 0, sB>>>(ent_emb, 1);
    cudaEventRecord(evB, sB);

    // chain C: relation-avg CSR + gather
    k_csr_cnt<<<gNZ1, TPB, 0, sC>>>(rel_adj, NZ, 2);
    k_scan<<<1, 1024, 0, sC>>>(2);
    k_fill_avg<<<gNZ1, TPB, 0, sC>>>(rel_adj, 2);
    k_avg_gather<<<gWN, TPB, 0, sC>>>(rel_emb, 2);
    cudaEventRecord(evC, sC);

    cudaStreamWaitEvent(0, evB, 0);
    cudaStreamWaitEvent(0, evC, 0);
    k_tanh0<<<gWN, TPB>>>();
    cudaStreamWaitEvent(0, evA, 0);
    k_gat_layer<<<gWN, TPB>>>(0, 0);
    k_gat_layer<<<gWN, TPB>>>(1, 1);

    k_pairstats<<<(BB * 32 + TPB - 1) / TPB, TPB>>>();
    k_nbmax<<<(NN + TPB - 1) / TPB, TPB>>>();
    k_scalecalc<<<(2 * BB + TPB - 1) / TPB, TPB>>>();

    cudaFuncSetAttribute(k_gemm_mma, cudaFuncAttributeMaxDynamicSharedMemorySize, NSTG * STGB);
    dim3 gg(2 * BB / 256, (NN + JT - 1) / JT);   // (8, 235)
    k_gemm_mma<<<gg, 512, NSTG * STGB>>>();
    k_row_exp<<<2 * BB, 256>>>();
    k_final<<<1, 256>>>(out);
}

// round 17
// speedup vs baseline: 1.0395x; 1.0395x over previous
#include <cuda_runtime.h>
#include <cuda_fp16.h>
#include <math.h>
#include <stdint.h>

#define NN 30000
#define RR 1000
#define TT 300000
#define DD 128
#define BB 1024
#define NZ 600000
#define OUTD 768
#define GAMMA_C 3.0f

// ---------------- scratch (device globals) ----------------
__device__ float g_relhat[RR * DD];
__device__ float g_elogit[4 * RR];
__device__ float g_s[4 * NN];
__device__ float g_featE[(size_t)NN * DD];
__device__ float g_featR[(size_t)NN * DD];
__device__ __half g_fcurhA[(size_t)NN * 256];
__device__ __half g_fcurhB[(size_t)NN * 256];
__device__ __half g_embh[(size_t)NN * OUTD];
__device__ float g_nb[NN];
__device__ float g_nbmax;
// adjacency CSR (GAT graph)
__device__ int g_rowptr[NN + 1];
__device__ int g_cursor[NN];
__device__ int g_ecol[TT];
__device__ int g_erel[TT];
// averaging CSRs
__device__ int g_rowptrE[NN + 1];
__device__ int g_curE[NN];
__device__ int g_ecolE[NZ];
__device__ int g_rowptrR[NN + 1];
__device__ int g_curR[NN];
__device__ int g_ecolR[NZ];
// loss
__device__ int   g_idxA[2 * BB];
__device__ float g_na[2 * BB];
__device__ float g_pos[BB];
__device__ int   g_lp[BB];
__device__ int   g_rp[BB];
__device__ float g_scale[2 * BB];
__device__ float g_iscale[2 * BB];
__device__ __align__(16) short g_Ss[(size_t)2 * BB * NN];  // int16 row-scaled S
__device__ double g_rsum[2 * BB];
__device__ double g_rsq[2 * BB];
__device__ float  g_rmax[2 * BB];
__device__ float g_lse[2 * BB];

__device__ __forceinline__ float warp_sum(float v) {
#pragma unroll
    for (int o = 16; o > 0; o >>= 1) v += __shfl_xor_sync(0xffffffffu, v, o);
    return v;
}
__device__ __forceinline__ float warp_max(float v) {
#pragma unroll
    for (int o = 16; o > 0; o >>= 1) v = fmaxf(v, __shfl_xor_sync(0xffffffffu, v, o));
    return v;
}
__device__ __forceinline__ void atomicMaxF(float* addr, float v) {
    if (v >= 0.f) atomicMax((int*)addr, __float_as_int(v));
    else          atomicMin((unsigned int*)addr, __float_as_uint(v));
}
__device__ __forceinline__ float fast_exp(float x) {
    float t = fmaxf(x * 1.4426950408889634f, -80.0f);
    float fl = floorf(t);
    float f = t - fl;
    float p = 0.0013333558f;
    p = fmaf(p, f, 0.0096181291f);
    p = fmaf(p, f, 0.0555041086f);
    p = fmaf(p, f, 0.2402264476f);
    p = fmaf(p, f, 0.6931471806f);
    p = fmaf(p, f, 1.0f);
    int i = (int)fl;
    return p * __int_as_float((i + 127) << 23);
}
__device__ __forceinline__ uint32_t smem_u32(const void* p) {
    uint32_t a;
    asm("{ .reg .u64 t; cvta.to.shared.u64 t, %1; cvt.u32.u64 %0, t; }" : "=r"(a) : "l"(p));
    return a;
}
__device__ __forceinline__ void cpasync16(uint32_t dst, const void* src) {
    asm volatile("cp.async.cg.shared.global [%0], [%1], 16;" :: "r"(dst), "l"(src));
}
__device__ __forceinline__ void ldsm4(uint32_t* r, uint32_t addr) {
    asm volatile("ldmatrix.sync.aligned.m8n8.x4.shared.b16 {%0,%1,%2,%3}, [%4];"
                 : "=r"(r[0]), "=r"(r[1]), "=r"(r[2]), "=r"(r[3]) : "r"(addr));
}
__device__ __forceinline__ void mma_f16(float* c, const uint32_t* a, const uint32_t* b) {
    asm volatile("mma.sync.aligned.m16n8k16.row.col.f32.f16.f16.f32 "
                 "{%0,%1,%2,%3}, {%4,%5,%6,%7}, {%8,%9}, {%0,%1,%2,%3};"
                 : "+f"(c[0]), "+f"(c[1]), "+f"(c[2]), "+f"(c[3])
                 : "r"(a[0]), "r"(a[1]), "r"(a[2]), "r"(a[3]), "r"(b[0]), "r"(b[1]));
}
__device__ __forceinline__ void st_half4(__half* dst, float a, float b, float c, float d) {
    __half2 h0 = __floats2half2_rn(a, b);
    __half2 h1 = __floats2half2_rn(c, d);
    *(uint2*)dst = make_uint2(*(uint32_t*)&h0, *(uint32_t*)&h1);
}
__device__ __forceinline__ float4 ld_half4(const __half* src) {
    uint2 u = *(const uint2*)src;
    float2 f0 = __half22float2(*(__half2*)&u.x);
    float2 f1 = __half22float2(*(__half2*)&u.y);
    return make_float4(f0.x, f0.y, f1.x, f1.y);
}
__device__ __forceinline__ int* cursor_of(int w) {
    return (w == 0) ? g_cursor : (w == 1) ? g_curE : g_curR;
}
__device__ __forceinline__ int* rowptr_of(int w) {
    return (w == 0) ? g_rowptr : (w == 1) ? g_rowptrE : g_rowptrR;
}

// ---------------- init ----------------
__global__ void k_init_stats() {
    int i = blockIdx.x * blockDim.x + threadIdx.x;
    if (i < NN) { g_nb[i] = 0.f; g_cursor[i] = 0; g_curE[i] = 0; g_curR[i] = 0; }
    if (i < 2 * BB) { g_rsum[i] = 0.0; g_rsq[i] = 0.0; g_rmax[i] = -3.0e38f; }
    if (i == 0) g_nbmax = 0.f;
}

// ---------------- relation prep ----------------
__global__ void k_relprep(const float* __restrict__ rel_emb,
                          const float* __restrict__ attn_e,
                          const float* __restrict__ attn_r) {
    int gid = blockIdx.x * blockDim.x + threadIdx.x;
    int r = gid >> 5;
    if (r >= RR) return;
    int lane = gid & 31;
    int d = lane * 4;
    float4 u = *(const float4*)&rel_emb[(size_t)r * DD + d];
    float ss = u.x * u.x + u.y * u.y + u.z * u.z + u.w * u.w;
    ss = warp_sum(ss);
    float inv = 1.f / fmaxf(sqrtf(ss), 1e-12f);
    u.x *= inv; u.y *= inv; u.z *= inv; u.w *= inv;
    *(float4*)&g_relhat[r * DD + d] = u;
    const float* ks[4] = { attn_e, attn_e + DD, attn_r, attn_r + DD };
#pragma unroll
    for (int c = 0; c < 4; c++) {
        const float4 kk = *(const float4*)&ks[c][d];
        float dot = u.x * kk.x + u.y * kk.y + u.z * kk.z + u.w * kk.w;
        dot = warp_sum(dot);
        if (lane == 0) g_elogit[c * RR + r] = fast_exp(dot);
    }
}

// ---------------- CSR build ----------------
__global__ void k_csr_cnt(const int* __restrict__ rows, int n, int w) {
    int t = blockIdx.x * blockDim.x + threadIdx.x;
    if (t >= n) return;
    atomicAdd(&cursor_of(w)[rows[t]], 1);
}
__global__ void k_scan(int w) {
    int* cur = cursor_of(w);
    int* rp = rowptr_of(w);
    __shared__ int warpsum[32];
    __shared__ int s_off;
    int tid = threadIdx.x, lane = tid & 31, wd = tid >> 5;
    if (tid == 0) s_off = 0;
    __syncthreads();
    for (int base = 0; base < NN; base += 1024) {
        int i = base + tid;
        int v = (i < NN) ? cur[i] : 0;
        int x = v;
#pragma unroll
        for (int o = 1; o < 32; o <<= 1) {
            int t2 = __shfl_up_sync(0xffffffffu, x, o);
            if (lane >= o) x += t2;
        }
        if (lane == 31) warpsum[wd] = x;
        __syncthreads();
        if (wd == 0) {
            int y = warpsum[lane];
#pragma unroll
            for (int o = 1; o < 32; o <<= 1) {
                int t2 = __shfl_up_sync(0xffffffffu, y, o);
                if (lane >= o) y += t2;
            }
            warpsum[lane] = y;
        }
        __syncthreads();
        int excl = x - v + (wd > 0 ? warpsum[wd - 1] : 0) + s_off;
        if (i < NN) { rp[i] = excl; cur[i] = excl; }
        __syncthreads();
        if (tid == 1023) s_off = excl + v;
        __syncthreads();
    }
    if (tid == 0) rp[NN] = s_off;
}
__global__ void k_fill_adj(const int* __restrict__ adj, const int* __restrict__ r_index) {
    int t = blockIdx.x * blockDim.x + threadIdx.x;
    if (t >= TT) return;
    int pos = atomicAdd(&g_cursor[adj[t]], 1);
    g_ecol[pos] = adj[TT + t];
    g_erel[pos] = r_index[TT + t];
}
__global__ void k_fill_avg(const int* __restrict__ eadj, int w) {
    int t = blockIdx.x * blockDim.x + threadIdx.x;
    if (t >= NZ) return;
    int* cur = (w == 1) ? g_curE : g_curR;
    int* ec = (w == 1) ? g_ecolE : g_ecolR;
    int pos = atomicAdd(&cur[eadj[t]], 1);
    ec[pos] = eadj[NZ + t];
}

// ---------------- per-row softmax denominators ----------------
__global__ void k_rowsm() {
    int gid = blockIdx.x * blockDim.x + threadIdx.x;
    int r = gid >> 5;
    if (r >= NN) return;
    int lane = gid & 31;
    int beg = g_rowptr[r], end = g_rowptr[r + 1];
    float s[4] = { 0.f, 0.f, 0.f, 0.f };
    for (int e = beg + lane; e < end; e += 32) {
        int rel = g_erel[e];
#pragma unroll
        for (int c = 0; c < 4; c++) s[c] += g_elogit[c * RR + rel];
    }
#pragma unroll
    for (int c = 0; c < 4; c++) {
        s[c] = warp_sum(s[c]);
        if (lane == 0) g_s[c * NN + r] = (s[c] > 0.f) ? 1.f / s[c] : 0.f;
    }
}

// ---------------- neighbor-average gather ----------------
__global__ void k_avg_gather(const float* __restrict__ src, int w) {
    int gid = blockIdx.x * blockDim.x + threadIdx.x;
    int r = gid >> 5;
    if (r >= NN) return;
    int lane = gid & 31;
    int d = lane * 4;
    const int* rp = (w == 1) ? g_rowptrE : g_rowptrR;
    const int* ec = (w == 1) ? g_ecolE : g_ecolR;
    float* feat = (w == 1) ? g_featE : g_featR;
    int beg = rp[r], end = rp[r + 1];
    float4 acc = make_float4(0, 0, 0, 0);
    for (int e = beg; e < end; e++) {
        int c = __ldg(&ec[e]);
        float4 v = *(const float4*)&src[(size_t)c * DD + d];
        acc.x += v.x; acc.y += v.y; acc.z += v.z; acc.w += v.w;
    }
    float inv = (end > beg) ? 1.f / (float)(end - beg) : 0.f;
    acc.x *= inv; acc.y *= inv; acc.z *= inv; acc.w *= inv;
    *(float4*)&feat[(size_t)r * DD + d] = acc;
}

// ---------------- initial tanh ----------------
__global__ void k_tanh0() {
    int gid = blockIdx.x * blockDim.x + threadIdx.x;
    int n = gid >> 5;
    if (n >= NN) return;
    int lane = gid & 31;
    int d = lane * 4;
    float4 fe = *(const float4*)&g_featE[(size_t)n * DD + d];
    float4 fr = *(const float4*)&g_featR[(size_t)n * DD + d];
    float vE0 = tanhf(fe.x), vE1 = tanhf(fe.y), vE2 = tanhf(fe.z), vE3 = tanhf(fe.w);
    float vR0 = tanhf(fr.x), vR1 = tanhf(fr.y), vR2 = tanhf(fr.z), vR3 = tanhf(fr.w);
    st_half4(&g_fcurhA[(size_t)n * 256 + d], vE0, vE1, vE2, vE3);
    st_half4(&g_fcurhA[(size_t)n * 256 + 128 + d], vR0, vR1, vR2, vR3);
    __half* hrow = &g_embh[(size_t)n * OUTD];
    st_half4(hrow + d, vE0, vE1, vE2, vE3);
    st_half4(hrow + 384 + d, vR0, vR1, vR2, vR3);
    float ss = 0.f;
    float q[8] = { vE0, vE1, vE2, vE3, vR0, vR1, vR2, vR3 };
#pragma unroll
    for (int k = 0; k < 8; k++) {
        float qq = __half2float(__float2half_rn(q[k]));
        ss += qq * qq;
    }
    ss = warp_sum(ss);
    if (lane == 0) atomicAdd(&g_nb[n], ss);
}

// ---------------- GAT layer ----------------
__global__ void k_gat_layer(int l, int dir) {
    int gid = blockIdx.x * blockDim.x + threadIdx.x;
    int r = gid >> 5;
    if (r >= NN) return;
    int lane = gid & 31;
    int d = lane * 4;
    const __half* src = dir ? g_fcurhB : g_fcurhA;
    __half* dst = dir ? g_fcurhA : g_fcurhB;
    int beg = g_rowptr[r], end = g_rowptr[r + 1];
    const int cE = l, cR = 2 + l;
    const float siE = g_s[cE * NN + r];
    const float siR = g_s[cR * NN + r];
    const float* elE = &g_elogit[cE * RR];
    const float* elR = &g_elogit[cR * RR];
    float4 accE = make_float4(0, 0, 0, 0), accR = make_float4(0, 0, 0, 0);
    for (int e = beg; e < end; e++) {
        int col = __ldg(&g_ecol[e]);
        int rel = __ldg(&g_erel[e]);
        float4 u = *(const float4*)&g_relhat[rel * DD + d];
        float4 xE = ld_half4(&src[(size_t)col * 256 + d]);
        float4 xR = ld_half4(&src[(size_t)col * 256 + 128 + d]);
        float dotE = warp_sum(xE.x * u.x + xE.y * u.y + xE.z * u.z + xE.w * u.w);
        float dotR = warp_sum(xR.x * u.x + xR.y * u.y + xR.z * u.z + xR.w * u.w);
        float wE = elE[rel] * siE;
        float wR = elR[rel] * siR;
        float sE = 2.f * dotE, sR = 2.f * dotR;
        accE.x += wE * (xE.x - sE * u.x); accE.y += wE * (xE.y - sE * u.y);
        accE.z += wE * (xE.z - sE * u.z); accE.w += wE * (xE.w - sE * u.w);
        accR.x += wR * (xR.x - sR * u.x); accR.y += wR * (xR.y - sR * u.y);
        accR.z += wR * (xR.z - sR * u.z); accR.w += wR * (xR.w - sR * u.w);
    }
    float vE0 = tanhf(accE.x), vE1 = tanhf(accE.y), vE2 = tanhf(accE.z), vE3 = tanhf(accE.w);
    float vR0 = tanhf(accR.x), vR1 = tanhf(accR.y), vR2 = tanhf(accR.z), vR3 = tanhf(accR.w);
    st_half4(&dst[(size_t)r * 256 + d], vE0, vE1, vE2, vE3);
    st_half4(&dst[(size_t)r * 256 + 128 + d], vR0, vR1, vR2, vR3);
    int base = (l + 1) * DD;
    __half* hrow = &g_embh[(size_t)r * OUTD];
    st_half4(hrow + base + d, vE0, vE1, vE2, vE3);
    st_half4(hrow + 384 + base + d, vR0, vR1, vR2, vR3);
    float ss = 0.f;
    float q[8] = { vE0, vE1, vE2, vE3, vR0, vR1, vR2, vR3 };
#pragma unroll
    for (int k = 0; k < 8; k++) {
        float qq = __half2float(__float2half_rn(q[k]));
        ss += qq * qq;
    }
    ss = warp_sum(ss);
    if (lane == 0) atomicAdd(&g_nb[r], ss);
}

// ---------------- loss prep ----------------
__global__ void k_prep_pairs(const int* __restrict__ pairs) {
    int p = blockIdx.x * blockDim.x + threadIdx.x;
    if (p >= BB) return;
    int lp = pairs[2 * p], rp = pairs[2 * p + 1];
    g_lp[p] = lp; g_rp[p] = rp;
    g_idxA[p] = lp; g_idxA[BB + p] = rp;
}
__global__ void k_pairstats() {
    int gid = blockIdx.x * blockDim.x + threadIdx.x;
    int p = gid >> 5;
    if (p >= BB) return;
    int lane = gid & 31;
    int lp = g_lp[p], rp = g_rp[p];
    const __half* a = &g_embh[(size_t)lp * OUTD];
    const __half* b = &g_embh[(size_t)rp * OUTD];
    float ss = 0.f;
    for (int k = lane * 4; k < OUTD; k += 128) {
        float4 av = ld_half4(&a[k]);
        float4 bv = ld_half4(&b[k]);
        float d0 = av.x - bv.x, d1 = av.y - bv.y, d2 = av.z - bv.z, d3 = av.w - bv.w;
        ss += d0 * d0 + d1 * d1 + d2 * d2 + d3 * d3;
    }
    ss = warp_sum(ss);
    if (lane == 0) { g_pos[p] = ss; g_na[p] = g_nb[lp]; }
    if (lane == 1) g_na[BB + p] = g_nb[rp];
}
__global__ void k_nbmax() {
    int i = blockIdx.x * blockDim.x + threadIdx.x;
    float v = (i < NN) ? g_nb[i] : 0.f;
    v = warp_max(v);
    __shared__ float sh[8];
    int lane = threadIdx.x & 31, wd = threadIdx.x >> 5;
    if (lane == 0) sh[wd] = v;
    __syncthreads();
    if (wd == 0) {
        v = (lane < 8) ? sh[lane] : 0.f;
        v = warp_max(v);
        if (lane == 0) atomicMaxF(&g_nbmax, v);
    }
}
__global__ void k_scalecalc() {
    int i = blockIdx.x * blockDim.x + threadIdx.x;
    if (i >= 2 * BB) return;
    int p = i & (BB - 1);
    float base = g_pos[p] - g_na[i] + GAMMA_C;
    float nbm = g_nbmax;
    float bound = fabsf(base) + nbm + 2.f * sqrtf(fmaxf(g_na[i], 0.f) * nbm) + 1.f;
    g_scale[i] = 32000.f / bound;
    g_iscale[i] = bound * (1.f / 32000.f);
}

// ---------------- mma.sync fp16 GEMM (128x128, 256 thr, occ 2) + int16 S + stats ----------------
#define JT 128
#define NS (OUTD / 16)
#define ROWB 48
#define STG_A 0
#define STG_B 6144
#define STGB 12288
#define NSTG 4

__global__ __launch_bounds__(256, 2) void k_gemm_mma() {
    extern __shared__ char dynsmem[];
    __shared__ int s_idx[128];
    const int tid = threadIdx.x;
    const int wid = tid >> 5;
    const int lane = tid & 31;
    const int warp_m = wid & 1;
    const int warp_n = wid >> 1;
    const int bm = blockIdx.x;
    const int jbase = blockIdx.y * JT;
    const uint32_t sbase = smem_u32(dynsmem);

    if (tid < 128) s_idx[tid] = g_idxA[bm * 128 + tid];
    __syncthreads();

    const int lrow = tid >> 1;
    const int lhalf = tid & 1;
    int jld = jbase + lrow;
    if (jld >= NN) jld = 0;
    const __half* gaPtr = g_embh + (size_t)s_idx[lrow] * OUTD + lhalf * 8;
    const __half* gbPtr = g_embh + (size_t)jld * OUTD + lhalf * 8;
    const uint32_t dOff = lrow * ROWB + lhalf * 16;

#pragma unroll
    for (int p = 0; p < 3; p++) {
        uint32_t sb = sbase + p * STGB;
        cpasync16(sb + STG_A + dOff, gaPtr + p * 16);
        cpasync16(sb + STG_B + dOff, gbPtr + p * 16);
        asm volatile("cp.async.commit_group;" ::: "memory");
    }

    float acc[4][4][4] = {};
    const int rsel = lane & 15;
    const int csel = (lane >> 4) * 16;

    for (int it = 0; it < NS; it++) {
        if (it < NS - 2)       asm volatile("cp.async.wait_group 2;" ::: "memory");
        else if (it == NS - 2) asm volatile("cp.async.wait_group 1;" ::: "memory");
        else                   asm volatile("cp.async.wait_group 0;" ::: "memory");
        __syncthreads();

        if (it + 3 < NS) {
            uint32_t sb = sbase + ((it + 3) & 3) * STGB;
            cpasync16(sb + STG_A + dOff, gaPtr + (it + 3) * 16);
            cpasync16(sb + STG_B + dOff, gbPtr + (it + 3) * 16);
            asm volatile("cp.async.commit_group;" ::: "memory");
        }

        const uint32_t sb = sbase + (it & 3) * STGB;
        uint32_t aF[4][4], bF[4][2];
#pragma unroll
        for (int mt = 0; mt < 4; mt++) {
            uint32_t ad = sb + STG_A + (uint32_t)((warp_m * 64 + mt * 16 + rsel) * ROWB + csel);
            ldsm4(aF[mt], ad);
        }
#pragma unroll
        for (int tp = 0; tp < 2; tp++) {
            uint32_t bd = sb + STG_B + (uint32_t)((warp_n * 32 + tp * 16 + rsel) * ROWB + csel);
            uint32_t r[4];
            ldsm4(r, bd);
            bF[tp * 2][0] = r[0]; bF[tp * 2][1] = r[2];
            bF[tp * 2 + 1][0] = r[1]; bF[tp * 2 + 1][1] = r[3];
        }
#pragma unroll
        for (int mt = 0; mt < 4; mt++)
#pragma unroll
            for (int nt = 0; nt < 4; nt++)
                mma_f16(acc[mt][nt], aF[mt], bF[nt]);
    }

    const int lq = lane >> 2;
    const int lr = lane & 3;
    float2 nbv[4];
#pragma unroll
    for (int nt = 0; nt < 4; nt++) {
        int j0 = jbase + warp_n * 32 + nt * 8 + 2 * lr;
        nbv[nt].x = (j0 < NN) ? g_nb[j0] : 0.f;
        nbv[nt].y = (j0 + 1 < NN) ? g_nb[j0 + 1] : 0.f;
    }
#pragma unroll
    for (int mt = 0; mt < 4; mt++) {
#pragma unroll
        for (int h = 0; h < 2; h++) {
            const int i = bm * 128 + warp_m * 64 + mt * 16 + lq + h * 8;
            const int p = i & (BB - 1);
            const float base = g_pos[p] - g_na[i] + GAMMA_C;
            const int lp = g_lp[p], rp = g_rp[p];
            const float sc = g_scale[i], isc = g_iscale[i];
            float s = 0.f, q = 0.f, mx = -3.0e38f;
            short* srow = &g_Ss[(size_t)i * NN];
#pragma unroll
            for (int nt = 0; nt < 4; nt++) {
                int j0 = jbase + warp_n * 32 + nt * 8 + 2 * lr;
                float c0 = acc[mt][nt][h * 2 + 0];
                float c1 = acc[mt][nt][h * 2 + 1];
                if (j0 + 1 < NN) {
                    float v0 = (base - nbv[nt].x + 2.f * c0) *
                               (1.f - (float)(j0 == lp) - (float)(j0 == rp));
                    float v1 = (base - nbv[nt].y + 2.f * c1) *
                               (1.f - (float)(j0 + 1 == lp) - (float)(j0 + 1 == rp));
                    int q0 = __float2int_rn(v0 * sc);
                    int q1 = __float2int_rn(v1 * sc);
                    q0 = max(-32767, min(32767, q0));
                    q1 = max(-32767, min(32767, q1));
                    *(short2*)&srow[j0] = make_short2((short)q0, (short)q1);
                    float d0 = (float)q0 * isc, d1 = (float)q1 * isc;
                    s += d0 + d1; q += d0 * d0 + d1 * d1;
                    mx = fmaxf(mx, fmaxf(d0, d1));
                } else if (j0 < NN) {
                    float v0 = (base - nbv[nt].x + 2.f * c0) *
                               (1.f - (float)(j0 == lp) - (float)(j0 == rp));
                    int q0 = __float2int_rn(v0 * sc);
                    q0 = max(-32767, min(32767, q0));
                    srow[j0] = (short)q0;
                    float d0 = (float)q0 * isc;
                    s += d0; q += d0 * d0; mx = fmaxf(mx, d0);
                }
            }
#pragma unroll
            for (int o = 1; o <= 2; o <<= 1) {
                s += __shfl_xor_sync(0xffffffffu, s, o);
                q += __shfl_xor_sync(0xffffffffu, q, o);
                mx = fmaxf(mx, __shfl_xor_sync(0xffffffffu, mx, o));
            }
            if (lr == 0) {
                atomicAdd(&g_rsum[i], (double)s);
                atomicAdd(&g_rsq[i], (double)q);
                atomicMaxF(&g_rmax[i], mx);
            }
        }
    }
}

// ---------------- per-row logsumexp (int16 S) ----------------
__global__ void k_row_exp() {
    int i = blockIdx.x;
    int tid = threadIdx.x;
    double mu_d = g_rsum[i] / NN;
    double var = g_rsq[i] / NN - mu_d * mu_d;
    if (var < 0.0) var = 0.0;
    double sd = sqrt(var);
    float mu = (float)mu_d;
    float inv = (float)(20.0 / sd);
    float zmax = (float)((g_rmax[i] - mu_d) * (20.0 / sd)) + 8.f;
    float qinv = g_iscale[i] * inv;
    float cterm = 8.f - zmax - mu * inv;
    const int4* row4 = (const int4*)(g_Ss + (size_t)i * NN);
    float es = 0.f;
    for (int j = tid; j < NN / 8; j += 256) {
        int4 v = row4[j];
        short2 s0 = *(short2*)&v.x, s1 = *(((short2*)&v.x) + 1);
        short2 s2 = *(short2*)&v.z, s3 = *(((short2*)&v.z) + 1);
        es += fast_exp(fmaf((float)s0.x, qinv, cterm));
        es += fast_exp(fmaf((float)s0.y, qinv, cterm));
        es += fast_exp(fmaf((float)s1.x, qinv, cterm));
        es += fast_exp(fmaf((float)s1.y, qinv, cterm));
        es += fast_exp(fmaf((float)s2.x, qinv, cterm));
        es += fast_exp(fmaf((float)s2.y, qinv, cterm));
        es += fast_exp(fmaf((float)s3.x, qinv, cterm));
        es += fast_exp(fmaf((float)s3.y, qinv, cterm));
    }
    __shared__ float sh[256];
    sh[tid] = es;
    __syncthreads();
    for (int o = 128; o > 0; o >>= 1) {
        if (tid < o) sh[tid] += sh[tid + o];
        __syncthreads();
    }
    if (tid == 0) g_lse[i] = zmax + logf(sh[0]);
}

__global__ void k_final(float* out) {
    int tid = threadIdx.x;
    double acc = 0.0;
    for (int p = tid; p < BB; p += 256) acc += (double)g_lse[p] + (double)g_lse[BB + p];
    __shared__ double sh[256];
    sh[tid] = acc;
    __syncthreads();
    for (int o = 128; o > 0; o >>= 1) {
        if (tid < o) sh[tid] += sh[tid + o];
        __syncthreads();
    }
    if (tid == 0) out[0] = (float)(sh[0] / BB);
}

// ---------------- driver ----------------
extern "C" void kernel_launch(void* const* d_in, const int* in_sizes, int n_in,
                              void* d_out, int out_size) {
    const float* ent_emb = (const float*)d_in[0];
    const float* rel_emb = (const float*)d_in[1];
    const float* attn_e  = (const float*)d_in[2];
    const float* attn_r  = (const float*)d_in[3];
    const int* adj     = (const int*)d_in[5];
    const int* r_index = (const int*)d_in[6];
    const int* ent_adj = (const int*)d_in[7];
    const int* rel_adj = (const int*)d_in[8];
    const int* pairs   = (const int*)d_in[9];
    float* out = (float*)d_out;

    static cudaStream_t sA = 0, sB = 0, sC = 0;
    static cudaEvent_t evRoot = 0, evA = 0, evB = 0, evC = 0;
    static bool sinit = false;
    if (!sinit) {
        cudaStreamCreateWithFlags(&sA, cudaStreamNonBlocking);
        cudaStreamCreateWithFlags(&sB, cudaStreamNonBlocking);
        cudaStreamCreateWithFlags(&sC, cudaStreamNonBlocking);
        cudaEventCreateWithFlags(&evRoot, cudaEventDisableTiming);
        cudaEventCreateWithFlags(&evA, cudaEventDisableTiming);
        cudaEventCreateWithFlags(&evB, cudaEventDisableTiming);
        cudaEventCreateWithFlags(&evC, cudaEventDisableTiming);
        sinit = true;
    }

    const int TPB = 256;
    const int gT   = (TT + TPB - 1) / TPB;
    const int gNZ1 = (NZ + TPB - 1) / TPB;
    const int gWN  = (NN * 32 + TPB - 1) / TPB;

    k_init_stats<<<(NN + TPB - 1) / TPB, TPB>>>();
    k_prep_pairs<<<(BB + TPB - 1) / TPB, TPB>>>(pairs);
    cudaEventRecord(evRoot, 0);
    cudaStreamWaitEvent(sA, evRoot, 0);
    cudaStreamWaitEvent(sB, evRoot, 0);
    cudaStreamWaitEvent(sC, evRoot, 0);

    // chain A: relation prep + adj CSR + softmax denominators
    k_relprep<<<(RR * 32 + TPB - 1) / TPB, TPB, 0, sA>>>(rel_emb, attn_e, attn_r);
    k_csr_cnt<<<gT, TPB, 0, sA>>>(adj, TT, 0);
    k_scan<<<1, 1024, 0, sA>>>(0);
    k_fill_adj<<<gT, TPB, 0, sA>>>(adj, r_index);
    k_rowsm<<<gWN, TPB, 0, sA>>>();
    cudaEventRecord(evA, sA);

    // chain B: entity-avg CSR + gather
    k_csr_cnt<<<gNZ1, TPB, 0, sB>>>(ent_adj, NZ, 1);
    k_scan<<<1, 1024, 0, sB>>>(1);
    k_fill_avg<<<gNZ1, TPB, 0, sB>>>(ent_adj, 1);
    k_avg_gather<<<gWN, TPB, 0, sB>>>(ent_emb, 1);
    cudaEventRecord(evB, sB);

    // chain C: relation-avg CSR + gather
    k_csr_cnt<<<gNZ1, TPB, 0, sC>>>(rel_adj, NZ, 2);
    k_scan<<<1, 1024, 0, sC>>>(2);
    k_fill_avg<<<gNZ1, TPB, 0, sC>>>(rel_adj, 2);
    k_avg_gather<<<gWN, TPB, 0, sC>>>(rel_emb, 2);
    cudaEventRecord(evC, sC);

    cudaStreamWaitEvent(0, evB, 0);
    cudaStreamWaitEvent(0, evC, 0);
    k_tanh0<<<gWN, TPB>>>();
    cudaStreamWaitEvent(0, evA, 0);
    k_gat_layer<<<gWN, TPB>>>(0, 0);
    k_gat_layer<<<gWN, TPB>>>(1, 1);

    k_pairstats<<<(BB * 32 + TPB - 1) / TPB, TPB>>>();
    k_nbmax<<<(NN + TPB - 1) / TPB, TPB>>>();
    k_scalecalc<<<(2 * BB + TPB - 1) / TPB, TPB>>>();

    cudaFuncSetAttribute(k_gemm_mma, cudaFuncAttributeMaxDynamicSharedMemorySize, NSTG * STGB);
    dim3 gg(2 * BB / 128, (NN + JT - 1) / JT);   // (16, 235)
    k_gemm_mma<<<gg, 256, NSTG * STGB>>>();
    k_row_exp<<<2 * BB, 256>>>();
    k_final<<<1, 256>>>(out);
}